// round 10
// baseline (speedup 1.0000x reference)
#include <cuda_runtime.h>
#include <cuda_bf16.h>
#include <cstdint>

// smem map (bytes), all 256B-stride XOR-swizzled rows:
//  XH/XL: X hi/lo, 256 rows x 128 bf16
//  XWH/XWL: XW hi/lo, 128 rows x 128 bf16 (XWL holds W-lo during GEMM1)
//  PW: 32KB, W-hi during GEMM1, then per-chunk P (rows q, [hi 128B | lo 128B])
#define XH_OFF 0
#define XL_OFF 65536
#define XWH_OFF 131072
#define XWL_OFF 163840
#define PW_OFF  196608
#define SUMA_OFF 229376
#define SUMM_OFF 230400
#define SMEM_TOTAL 231424

__device__ __forceinline__ uint32_t smem_u32(const void* p) {
    uint32_t a;
    asm("{ .reg .u64 t; cvta.to.shared.u64 t, %1; cvt.u32.u64 %0, t; }" : "=r"(a) : "l"(p));
    return a;
}
__device__ __forceinline__ uint32_t soff(uint32_t region, int row, int byte) {
    return region + (uint32_t)(row * 256 + (byte ^ ((row & 7) << 4)));
}
__device__ __forceinline__ void ldsm4(uint32_t addr, uint32_t (&r)[4]) {
    asm volatile("ldmatrix.sync.aligned.m8n8.x4.shared.b16 {%0,%1,%2,%3}, [%4];"
                 : "=r"(r[0]), "=r"(r[1]), "=r"(r[2]), "=r"(r[3]) : "r"(addr));
}
__device__ __forceinline__ void ldsm4t(uint32_t addr, uint32_t (&r)[4]) {
    asm volatile("ldmatrix.sync.aligned.m8n8.x4.trans.shared.b16 {%0,%1,%2,%3}, [%4];"
                 : "=r"(r[0]), "=r"(r[1]), "=r"(r[2]), "=r"(r[3]) : "r"(addr));
}
__device__ __forceinline__ void mma16816(float (&c)[4], const uint32_t (&a)[4],
                                         uint32_t b0, uint32_t b1) {
    asm volatile("mma.sync.aligned.m16n8k16.row.col.f32.bf16.bf16.f32 "
                 "{%0,%1,%2,%3}, {%4,%5,%6,%7}, {%8,%9}, {%0,%1,%2,%3};"
                 : "+f"(c[0]), "+f"(c[1]), "+f"(c[2]), "+f"(c[3])
                 : "r"(a[0]), "r"(a[1]), "r"(a[2]), "r"(a[3]), "r"(b0), "r"(b1));
}
__device__ __forceinline__ uint32_t bpack(float x, float y) {
    __nv_bfloat162 h = __floats2bfloat162_rn(x, y);
    return *reinterpret_cast<uint32_t*>(&h);
}
__device__ __forceinline__ uint32_t bpacklo(float x, float y) {
    float hx = __bfloat162float(__float2bfloat16_rn(x));
    float hy = __bfloat162float(__float2bfloat16_rn(y));
    return bpack(x - hx, y - hy);
}
#define BARP(id) asm volatile("bar.sync %0, %1;" :: "r"(id), "r"(64) : "memory")

__global__ void __launch_bounds__(256, 1)
sattn_mma_kernel(const float* __restrict__ words, const float* __restrict__ Wm,
                 const int* __restrict__ vlen, float* __restrict__ out)
{
    extern __shared__ __align__(1024) char smem[];
    const uint32_t sb = smem_u32(smem);
    const int tid = threadIdx.x, lane = tid & 31, warp = tid >> 5;
    const int pair = warp >> 1, side = warp & 1, barid = 1 + pair;
    const int sent = blockIdx.x >> 1, q0 = (blockIdx.x & 1) * 128;
    const float* xg = words + (size_t)sent * 256 * 128;
    const int len = vlen[sent];
    const int g = lane >> 2, q4 = lane & 3;
    const int qr = pair * 32;                 // pair's CTA-local query-row base

    // ---- load X -> XH/XL ----
    for (int i = tid; i < 8192; i += 256) {
        float4 v = ((const float4*)xg)[i];
        int t = i >> 5, b = (i & 31) << 3;
        uint2 hw, lw;
        hw.x = bpack(v.x, v.y); hw.y = bpack(v.z, v.w);
        lw.x = bpacklo(v.x, v.y); lw.y = bpacklo(v.z, v.w);
        *(uint2*)(smem + soff(XH_OFF, t, b)) = hw;
        *(uint2*)(smem + soff(XL_OFF, t, b)) = lw;
    }
    // ---- load W ([k][n]): hi -> PW region, lo -> XWL region ----
    for (int i = tid; i < 4096; i += 256) {
        float4 v = ((const float4*)Wm)[i];
        int k = i >> 5, b = (i & 31) << 3;
        uint2 hw, lw;
        hw.x = bpack(v.x, v.y); hw.y = bpack(v.z, v.w);
        lw.x = bpacklo(v.x, v.y); lw.y = bpacklo(v.z, v.w);
        *(uint2*)(smem + soff(PW_OFF, k, b)) = hw;
        *(uint2*)(smem + soff(XWL_OFF, k, b)) = lw;
    }
    __syncthreads();

    // ===== GEMM1: XW[pair 32q x side 64c] = Xq @ W (3 passes, B loaded once) =====
    {
        float xw[2][8][4];
        #pragma unroll
        for (int mb = 0; mb < 2; ++mb)
            #pragma unroll
            for (int u = 0; u < 8; ++u)
                xw[mb][u][0] = xw[mb][u][1] = xw[mb][u][2] = xw[mb][u][3] = 0.f;

        #pragma unroll
        for (int kt = 0; kt < 8; ++kt) {
            uint32_t Ah[2][4], Al[2][4];
            #pragma unroll
            for (int mb = 0; mb < 2; ++mb) {
                int row = q0 + qr + mb * 16 + (lane & 15);
                int byt = kt * 32 + ((lane >> 4) << 4);
                ldsm4(sb + soff(XH_OFF, row, byt), Ah[mb]);
                ldsm4(sb + soff(XL_OFF, row, byt), Al[mb]);
            }
            const int rr = kt * 16 + (lane & 7) + (((lane >> 3) & 1) << 3);
            uint32_t Bh[4][4], Bl[4][4];
            #pragma unroll
            for (int nn = 0; nn < 4; ++nn) {
                int bb = ((side * 64 + nn * 16) + ((lane >> 4) << 3)) * 2;
                ldsm4t(sb + soff(PW_OFF, rr, bb), Bh[nn]);
                ldsm4t(sb + soff(XWL_OFF, rr, bb), Bl[nn]);
            }
            #pragma unroll
            for (int mb = 0; mb < 2; ++mb)
                #pragma unroll
                for (int nn = 0; nn < 4; ++nn) {
                    mma16816(xw[mb][2 * nn],     Ah[mb], Bh[nn][0], Bh[nn][1]);
                    mma16816(xw[mb][2 * nn + 1], Ah[mb], Bh[nn][2], Bh[nn][3]);
                }
            #pragma unroll
            for (int mb = 0; mb < 2; ++mb)
                #pragma unroll
                for (int nn = 0; nn < 4; ++nn) {
                    mma16816(xw[mb][2 * nn],     Al[mb], Bh[nn][0], Bh[nn][1]);
                    mma16816(xw[mb][2 * nn + 1], Al[mb], Bh[nn][2], Bh[nn][3]);
                }
            #pragma unroll
            for (int mb = 0; mb < 2; ++mb)
                #pragma unroll
                for (int nn = 0; nn < 4; ++nn) {
                    mma16816(xw[mb][2 * nn],     Ah[mb], Bl[nn][0], Bl[nn][1]);
                    mma16816(xw[mb][2 * nn + 1], Ah[mb], Bl[nn][2], Bl[nn][3]);
                }
        }
        __syncthreads();   // all warps done reading W-hi / W-lo

        // store XW hi/lo (own 64-col slice)
        #pragma unroll
        for (int mb = 0; mb < 2; ++mb)
            #pragma unroll
            for (int u = 0; u < 8; ++u) {
                int nbyte = 2 * (side * 64 + 8 * u + 2 * q4);
                int rA = qr + mb * 16 + g, rB = rA + 8;
                *(uint32_t*)(smem + soff(XWH_OFF, rA, nbyte)) = bpack(xw[mb][u][0], xw[mb][u][1]);
                *(uint32_t*)(smem + soff(XWL_OFF, rA, nbyte)) = bpacklo(xw[mb][u][0], xw[mb][u][1]);
                *(uint32_t*)(smem + soff(XWH_OFF, rB, nbyte)) = bpack(xw[mb][u][2], xw[mb][u][3]);
                *(uint32_t*)(smem + soff(XWL_OFF, rB, nbyte)) = bpacklo(xw[mb][u][2], xw[mb][u][3]);
            }
    }
    BARP(barid);   // pair's full XW visible

    // ===== per 64-key chunk: GEMM2 (own 32 keys) -> exp/mask -> P to smem ->
    //       pair bar -> GEMM3 (all 64 keys, own 64 cols) =====
    float oa[2][4][2][4];
    #pragma unroll
    for (int mb = 0; mb < 2; ++mb)
        #pragma unroll
        for (int nn = 0; nn < 4; ++nn)
            #pragma unroll
            for (int h = 0; h < 2; ++h)
                oa[mb][nn][h][0] = oa[mb][nn][h][1] = oa[mb][nn][h][2] = oa[mb][nn][h][3] = 0.f;
    float sa[2][2] = {{0.f, 0.f}, {0.f, 0.f}}, sm_[2][2] = {{0.f, 0.f}, {0.f, 0.f}};

    #pragma unroll 1
    for (int c = 0; c < 4; ++c) {
        const int kb = c * 64 + side * 32;
        float la[2][2][2][4];
        #pragma unroll
        for (int mb = 0; mb < 2; ++mb)
            #pragma unroll
            for (int nb = 0; nb < 2; ++nb)
                #pragma unroll
                for (int h = 0; h < 2; ++h)
                    la[mb][nb][h][0] = la[mb][nb][h][1] = la[mb][nb][h][2] = la[mb][nb][h][3] = 0.f;

        // ---- GEMM2: L[32q x 32k] = XW @ X[kb..kb+32]^T ----
        #pragma unroll
        for (int kt = 0; kt < 8; ++kt) {
            uint32_t Ah[2][4], Al[2][4];
            #pragma unroll
            for (int mb = 0; mb < 2; ++mb) {
                int row = qr + mb * 16 + (lane & 15);
                int byt = kt * 32 + ((lane >> 4) << 4);
                ldsm4(sb + soff(XWH_OFF, row, byt), Ah[mb]);
                ldsm4(sb + soff(XWL_OFF, row, byt), Al[mb]);
            }
            uint32_t Bh[2][4], Bl[2][4];
            #pragma unroll
            for (int nb = 0; nb < 2; ++nb) {
                int rr = kb + nb * 16 + (lane & 7) + ((lane >> 4) << 3);
                int bb = kt * 32 + (((lane >> 3) & 1) << 4);
                ldsm4(sb + soff(XH_OFF, rr, bb), Bh[nb]);
                ldsm4(sb + soff(XL_OFF, rr, bb), Bl[nb]);
            }
            #pragma unroll
            for (int mb = 0; mb < 2; ++mb)
                #pragma unroll
                for (int nb = 0; nb < 2; ++nb) {
                    mma16816(la[mb][nb][0], Ah[mb], Bh[nb][0], Bh[nb][1]);
                    mma16816(la[mb][nb][1], Ah[mb], Bh[nb][2], Bh[nb][3]);
                }
            #pragma unroll
            for (int mb = 0; mb < 2; ++mb)
                #pragma unroll
                for (int nb = 0; nb < 2; ++nb) {
                    mma16816(la[mb][nb][0], Ah[mb], Bl[nb][0], Bl[nb][1]);
                    mma16816(la[mb][nb][1], Ah[mb], Bl[nb][2], Bl[nb][3]);
                }
            #pragma unroll
            for (int mb = 0; mb < 2; ++mb)
                #pragma unroll
                for (int nb = 0; nb < 2; ++nb) {
                    mma16816(la[mb][nb][0], Al[mb], Bh[nb][0], Bh[nb][1]);
                    mma16816(la[mb][nb][1], Al[mb], Bh[nb][2], Bh[nb][3]);
                }
        }

        // ---- tanh -> exp -> mask (unnormalized; sums accumulated) ----
        #pragma unroll
        for (int mb = 0; mb < 2; ++mb)
            #pragma unroll
            for (int nb = 0; nb < 2; ++nb)
                #pragma unroll
                for (int h = 0; h < 2; ++h) {
                    int tb = kb + nb * 16 + h * 8 + 2 * q4;
                    #pragma unroll
                    for (int ch = 0; ch < 2; ++ch) {
                        const bool m = (tb + ch) < len;
                        {
                            float l = la[mb][nb][h][ch];
                            float u = __expf(2.f * l);
                            float t2 = 1.f - __fdividef(2.f, u + 1.f);
                            float w = __expf(t2);
                            float wm = m ? w : 0.f;
                            sa[mb][0] += w; sm_[mb][0] += wm; la[mb][nb][h][ch] = wm;
                        }
                        {
                            float l = la[mb][nb][h][2 + ch];
                            float u = __expf(2.f * l);
                            float t2 = 1.f - __fdividef(2.f, u + 1.f);
                            float w = __expf(t2);
                            float wm = m ? w : 0.f;
                            sa[mb][1] += w; sm_[mb][1] += wm; la[mb][nb][h][2 + ch] = wm;
                        }
                    }
                }

        // ---- P -> smem (bf16 hi/lo within one 256B row) ----
        #pragma unroll
        for (int mb = 0; mb < 2; ++mb)
            #pragma unroll
            for (int nb = 0; nb < 2; ++nb)
                #pragma unroll
                for (int h = 0; h < 2; ++h) {
                    int pb = 2 * (side * 32 + nb * 16 + h * 8 + 2 * q4);
                    int rA = qr + mb * 16 + g, rB = rA + 8;
                    *(uint32_t*)(smem + soff(PW_OFF, rA, pb)) = bpack(la[mb][nb][h][0], la[mb][nb][h][1]);
                    *(uint32_t*)(smem + soff(PW_OFF, rA, 128 + pb)) = bpacklo(la[mb][nb][h][0], la[mb][nb][h][1]);
                    *(uint32_t*)(smem + soff(PW_OFF, rB, pb)) = bpack(la[mb][nb][h][2], la[mb][nb][h][3]);
                    *(uint32_t*)(smem + soff(PW_OFF, rB, 128 + pb)) = bpacklo(la[mb][nb][h][2], la[mb][nb][h][3]);
                }
        BARP(barid);

        // ---- GEMM3: oa += P[32q x 64k] @ X[c*64..+64, side 64 cols] ----
        #pragma unroll
        for (int kt2 = 0; kt2 < 4; ++kt2) {
            uint32_t Ph[2][4], Pl[2][4];
            #pragma unroll
            for (int mb = 0; mb < 2; ++mb) {
                int row = qr + mb * 16 + (lane & 15);
                int byt = kt2 * 32 + ((lane >> 4) << 4);
                ldsm4(sb + soff(PW_OFF, row, byt), Ph[mb]);
                ldsm4(sb + soff(PW_OFF, row, 128 + byt), Pl[mb]);
            }
            const int rr = c * 64 + kt2 * 16 + (lane & 7) + (((lane >> 3) & 1) << 3);
            uint32_t Bh[4][4], Bl[4][4];
            #pragma unroll
            for (int nn = 0; nn < 4; ++nn) {
                int bb = ((side * 64 + nn * 16) + ((lane >> 4) << 3)) * 2;
                ldsm4t(sb + soff(XH_OFF, rr, bb), Bh[nn]);
                ldsm4t(sb + soff(XL_OFF, rr, bb), Bl[nn]);
            }
            #pragma unroll
            for (int mb = 0; mb < 2; ++mb)
                #pragma unroll
                for (int nn = 0; nn < 4; ++nn) {
                    mma16816(oa[mb][nn][0], Ph[mb], Bh[nn][0], Bh[nn][1]);
                    mma16816(oa[mb][nn][1], Ph[mb], Bh[nn][2], Bh[nn][3]);
                }
            #pragma unroll
            for (int mb = 0; mb < 2; ++mb)
                #pragma unroll
                for (int nn = 0; nn < 4; ++nn) {
                    mma16816(oa[mb][nn][0], Ph[mb], Bl[nn][0], Bl[nn][1]);
                    mma16816(oa[mb][nn][1], Ph[mb], Bl[nn][2], Bl[nn][3]);
                }
            #pragma unroll
            for (int mb = 0; mb < 2; ++mb)
                #pragma unroll
                for (int nn = 0; nn < 4; ++nn) {
                    mma16816(oa[mb][nn][0], Pl[mb], Bh[nn][0], Bh[nn][1]);
                    mma16816(oa[mb][nn][1], Pl[mb], Bh[nn][2], Bh[nn][3]);
                }
        }
        BARP(barid);   // P region safe to overwrite next chunk
    }

    // ===== sums: quad-reduce, exchange across pair, normalize, store =====
    #pragma unroll
    for (int off = 1; off <= 2; off <<= 1)
        #pragma unroll
        for (int mb = 0; mb < 2; ++mb)
            #pragma unroll
            for (int rs = 0; rs < 2; ++rs) {
                sa[mb][rs] += __shfl_xor_sync(0xffffffffu, sa[mb][rs], off);
                sm_[mb][rs] += __shfl_xor_sync(0xffffffffu, sm_[mb][rs], off);
            }
    if (q4 == 0) {
        #pragma unroll
        for (int mb = 0; mb < 2; ++mb)
            #pragma unroll
            for (int rs = 0; rs < 2; ++rs) {
                int idx = warp * 32 + mb * 16 + rs * 8 + g;
                *(float*)(smem + SUMA_OFF + idx * 4) = sa[mb][rs];
                *(float*)(smem + SUMM_OFF + idx * 4) = sm_[mb][rs];
            }
    }
    BARP(barid);

    float inv[2][2];
    #pragma unroll
    for (int mb = 0; mb < 2; ++mb)
        #pragma unroll
        for (int rs = 0; rs < 2; ++rs) {
            int i0 = warp * 32 + mb * 16 + rs * 8 + g;
            int i1 = (warp ^ 1) * 32 + mb * 16 + rs * 8 + g;
            float A = *(float*)(smem + SUMA_OFF + i0 * 4) + *(float*)(smem + SUMA_OFF + i1 * 4);
            float M = *(float*)(smem + SUMM_OFF + i0 * 4) + *(float*)(smem + SUMM_OFF + i1 * 4);
            inv[mb][rs] = 1.f / (M + 1e-8f * A);
        }

    {
        const size_t rbase = (size_t)sent * 256 + q0 + qr;
        #pragma unroll
        for (int mb = 0; mb < 2; ++mb)
            #pragma unroll
            for (int nn = 0; nn < 4; ++nn)
                #pragma unroll
                for (int h = 0; h < 2; ++h) {
                    int col = side * 64 + nn * 16 + h * 8 + 2 * q4;
                    float2 v0, v1;
                    v0.x = oa[mb][nn][h][0] * inv[mb][0]; v0.y = oa[mb][nn][h][1] * inv[mb][0];
                    v1.x = oa[mb][nn][h][2] * inv[mb][1]; v1.y = oa[mb][nn][h][3] * inv[mb][1];
                    *(float2*)(out + (rbase + mb * 16 + g) * 128 + col) = v0;
                    *(float2*)(out + (rbase + mb * 16 + g + 8) * 128 + col) = v1;
                }
    }
}

extern "C" void kernel_launch(void* const* d_in, const int* in_sizes, int n_in,
                              void* d_out, int out_size)
{
    const float* words = (const float*)d_in[0];
    const float* Wm    = (const float*)d_in[1];
    const int*   vlen  = (const int*)d_in[2];
    float* out = (float*)d_out;

    cudaFuncSetAttribute(sattn_mma_kernel,
                         cudaFuncAttributeMaxDynamicSharedMemorySize, SMEM_TOTAL);
    sattn_mma_kernel<<<1024, 256, SMEM_TOTAL>>>(words, Wm, vlen, out);
}